// round 2
// baseline (speedup 1.0000x reference)
#include <cuda_runtime.h>
#include <math.h>

#define NNODES 20000
#define NEDGES 640000
#define DMODEL 512
#define NHEAD 8
#define DHEAD 64
#define DFFN 2048

// ---------------- scratch (no allocs allowed) ----------------
__device__ float g_q[(size_t)NNODES * DMODEL];
__device__ float g_k[(size_t)NNODES * DMODEL];
__device__ float g_v[(size_t)NNODES * DMODEL];
__device__ float g_a[(size_t)NNODES * DMODEL];
__device__ float g_o[(size_t)NNODES * DMODEL];
__device__ float g_x[(size_t)NNODES * DMODEL];
__device__ float g_y[(size_t)NNODES * DMODEL];
__device__ float g_f[(size_t)NNODES * DFFN];
__device__ float g_e[(size_t)NEDGES * NHEAD];
__device__ int   g_rowptr[NNODES + 1];

// ---------------- CSR row pointers from sorted dst ----------------
__global__ void build_rowptr(const int* __restrict__ dst) {
    int i = blockIdx.x * blockDim.x + threadIdx.x;
    if (i > NNODES) return;
    int lo = 0, hi = NEDGES;
    while (lo < hi) {
        int mid = (lo + hi) >> 1;
        if (dst[mid] < i) lo = mid + 1; else hi = mid;
    }
    g_rowptr[i] = lo;
}

// ---------------- generic fp32 tiled GEMM: C = A[MxK] @ B[KxN] (+bias)(+relu) ----------------
// BM=BN=128, BK=16, 256 threads, 8x8 micro-tile with strided mapping.
template<bool BIAS, bool RELU>
__global__ __launch_bounds__(256)
void gemm128(const float* __restrict__ A, const float* __restrict__ B,
             const float* __restrict__ bias, float* __restrict__ C,
             int M, int N, int K)
{
    __shared__ float As[16][128];
    __shared__ float Bs[16][128];
    const int tid = threadIdx.x;
    const int tx = tid & 15;          // N micro index
    const int ty = tid >> 4;          // M micro index
    const int row0 = blockIdx.y * 128;
    const int col0 = blockIdx.x * 128;

    float acc[8][8];
#pragma unroll
    for (int i = 0; i < 8; i++)
#pragma unroll
        for (int j = 0; j < 8; j++) acc[i][j] = 0.f;

    for (int k0 = 0; k0 < K; k0 += 16) {
        // load A tile 128x16 (transposed into As[k][m])
#pragma unroll
        for (int s = 0; s < 2; s++) {
            int idx = tid + s * 256;
            int r = idx >> 2;
            int c = (idx & 3) << 2;
            int gr = row0 + r;
            float4 av = make_float4(0.f, 0.f, 0.f, 0.f);
            if (gr < M) av = *(const float4*)(A + (size_t)gr * K + k0 + c);
            As[c + 0][r] = av.x; As[c + 1][r] = av.y;
            As[c + 2][r] = av.z; As[c + 3][r] = av.w;
        }
        // load B tile 16x128
#pragma unroll
        for (int s = 0; s < 2; s++) {
            int idx = tid + s * 256;
            int r = idx >> 5;
            int c = (idx & 31) << 2;
            float4 bv = *(const float4*)(B + (size_t)(k0 + r) * N + col0 + c);
            *(float4*)&Bs[r][c] = bv;
        }
        __syncthreads();
#pragma unroll
        for (int k = 0; k < 16; k++) {
            float ar[8], br[8];
#pragma unroll
            for (int i = 0; i < 8; i++) ar[i] = As[k][ty + i * 16];
#pragma unroll
            for (int j = 0; j < 8; j++) br[j] = Bs[k][tx + j * 16];
#pragma unroll
            for (int i = 0; i < 8; i++)
#pragma unroll
                for (int j = 0; j < 8; j++)
                    acc[i][j] = fmaf(ar[i], br[j], acc[i][j]);
        }
        __syncthreads();
    }
#pragma unroll
    for (int i = 0; i < 8; i++) {
        int gr = row0 + ty + i * 16;
        if (gr >= M) continue;
#pragma unroll
        for (int j = 0; j < 8; j++) {
            int gc = col0 + tx + j * 16;
            float v = acc[i][j];
            if (BIAS) v += bias[gc];
            if (RELU) v = fmaxf(v, 0.f);
            C[(size_t)gr * N + gc] = v;
        }
    }
}

// ---------------- edge scores: e[E,H] = (k[src] . q[dst]) per head / sqrt(DK) ----------------
__device__ __forceinline__ float dot4(float4 a, float4 b) {
    return a.x * b.x + a.y * b.y + a.z * b.z + a.w * b.w;
}

__global__ __launch_bounds__(256)
void edge_scores(const int* __restrict__ src, const int* __restrict__ dst) {
    int e = (int)((blockIdx.x * blockDim.x + threadIdx.x) >> 5);
    int lane = threadIdx.x & 31;
    if (e >= NEDGES) return;
    const float4* kk = (const float4*)(g_k + (size_t)src[e] * DMODEL);
    const float4* qq = (const float4*)(g_q + (size_t)dst[e] * DMODEL);
    // float4 index f = lane + 32*j ; head(f) = f/16 -> lane/16 + 2*j
    float p0 = dot4(kk[lane +  0], qq[lane +  0]);
    float p1 = dot4(kk[lane + 32], qq[lane + 32]);
    float p2 = dot4(kk[lane + 64], qq[lane + 64]);
    float p3 = dot4(kk[lane + 96], qq[lane + 96]);
#pragma unroll
    for (int off = 8; off; off >>= 1) {
        p0 += __shfl_xor_sync(0xffffffffu, p0, off);
        p1 += __shfl_xor_sync(0xffffffffu, p1, off);
        p2 += __shfl_xor_sync(0xffffffffu, p2, off);
        p3 += __shfl_xor_sync(0xffffffffu, p3, off);
    }
    if ((lane & 15) == 0) {
        int h0 = lane >> 4;  // 0 or 1
        float* out = g_e + (size_t)e * NHEAD;
        out[h0 + 0] = p0 * 0.125f;
        out[h0 + 2] = p1 * 0.125f;
        out[h0 + 4] = p2 * 0.125f;
        out[h0 + 6] = p3 * 0.125f;
    }
}

// ---------------- per-node softmax + weighted aggregation of v[src] ----------------
__global__ __launch_bounds__(128)
void node_aggregate(const int* __restrict__ src) {
    int node = blockIdx.x;
    int t = threadIdx.x;              // 128
    int beg = g_rowptr[node];
    int end = g_rowptr[node + 1];

    __shared__ float s_m[NHEAD];
    __shared__ float s_rz[NHEAD];

    // phases 1+2: 8 groups of 16 threads, one head per group
    int head = t >> 4;
    int sub  = t & 15;
    float mx = -INFINITY;
    for (int e = beg + sub; e < end; e += 16)
        mx = fmaxf(mx, g_e[(size_t)e * NHEAD + head]);
#pragma unroll
    for (int off = 8; off; off >>= 1)
        mx = fmaxf(mx, __shfl_xor_sync(0xffffffffu, mx, off));
    float sum = 0.f;
    for (int e = beg + sub; e < end; e += 16)
        sum += __expf(g_e[(size_t)e * NHEAD + head] - mx);
#pragma unroll
    for (int off = 8; off; off >>= 1)
        sum += __shfl_xor_sync(0xffffffffu, sum, off);
    if (sub == 0) {
        s_m[head] = mx;
        s_rz[head] = (end > beg) ? (1.f / sum) : 0.f;
    }
    __syncthreads();

    // phase 3: thread t owns cols [4t, 4t+4) (single head h2 = t/16); accumulate in regs
    int col = t << 2;
    int h2 = t >> 4;
    float m = s_m[h2], rz = s_rz[h2];
    float4 acc = make_float4(0.f, 0.f, 0.f, 0.f);
    for (int e = beg; e < end; e++) {
        float w = __expf(g_e[(size_t)e * NHEAD + h2] - m) * rz;
        int sv = src[e];
        float4 vv = *(const float4*)(g_v + (size_t)sv * DMODEL + col);
        acc.x = fmaf(w, vv.x, acc.x);
        acc.y = fmaf(w, vv.y, acc.y);
        acc.z = fmaf(w, vv.z, acc.z);
        acc.w = fmaf(w, vv.w, acc.w);
    }
    *(float4*)(g_a + (size_t)node * DMODEL + col) = acc;
}

// ---------------- residual + layernorm: out = LN(A + B) * gamma + beta ----------------
__global__ __launch_bounds__(128)
void residual_ln(const float* __restrict__ A, const float* __restrict__ B,
                 const float* __restrict__ gamma, const float* __restrict__ beta,
                 float* __restrict__ out)
{
    int row = blockIdx.x;
    int t = threadIdx.x;   // 128, each owns one float4 (512 total)
    float4 va = ((const float4*)(A + (size_t)row * DMODEL))[t];
    float4 vb = ((const float4*)(B + (size_t)row * DMODEL))[t];
    float4 v = make_float4(va.x + vb.x, va.y + vb.y, va.z + vb.z, va.w + vb.w);

    __shared__ float sh1[4], sh2[4];
    float s = v.x + v.y + v.z + v.w;
#pragma unroll
    for (int off = 16; off; off >>= 1) s += __shfl_xor_sync(0xffffffffu, s, off);
    if ((t & 31) == 0) sh1[t >> 5] = s;
    __syncthreads();
    float mu = (sh1[0] + sh1[1] + sh1[2] + sh1[3]) * (1.f / DMODEL);

    float dx = v.x - mu, dy = v.y - mu, dz = v.z - mu, dw = v.w - mu;
    float ss = dx * dx + dy * dy + dz * dz + dw * dw;
#pragma unroll
    for (int off = 16; off; off >>= 1) ss += __shfl_xor_sync(0xffffffffu, ss, off);
    if ((t & 31) == 0) sh2[t >> 5] = ss;
    __syncthreads();
    float var = (sh2[0] + sh2[1] + sh2[2] + sh2[3]) * (1.f / DMODEL);
    float rstd = rsqrtf(var + 1e-5f);

    float4 g = ((const float4*)gamma)[t];
    float4 be = ((const float4*)beta)[t];
    float4 o;
    o.x = dx * rstd * g.x + be.x;
    o.y = dy * rstd * g.y + be.y;
    o.z = dz * rstd * g.z + be.z;
    o.w = dw * rstd * g.w + be.w;
    ((float4*)(out + (size_t)row * DMODEL))[t] = o;
}

// ---------------- launch ----------------
extern "C" void kernel_launch(void* const* d_in, const int* in_sizes, int n_in,
                              void* d_out, int out_size)
{
    const float* h    = (const float*)d_in[0];
    const int*   src  = (const int*)d_in[1];
    const int*   dst  = (const int*)d_in[2];
    const float* Wq   = (const float*)d_in[3];
    const float* Wk   = (const float*)d_in[4];
    const float* Wv   = (const float*)d_in[5];
    const float* Wo   = (const float*)d_in[6];
    const float* ln1g = (const float*)d_in[7];
    const float* ln1b = (const float*)d_in[8];
    const float* ln2g = (const float*)d_in[9];
    const float* ln2b = (const float*)d_in[10];
    const float* W1   = (const float*)d_in[11];
    const float* b1   = (const float*)d_in[12];
    const float* W2   = (const float*)d_in[13];
    const float* b2   = (const float*)d_in[14];
    float* out = (float*)d_out;

    float *q, *k, *v, *a, *o, *x, *y, *f;
    cudaGetSymbolAddress((void**)&q, g_q);
    cudaGetSymbolAddress((void**)&k, g_k);
    cudaGetSymbolAddress((void**)&v, g_v);
    cudaGetSymbolAddress((void**)&a, g_a);
    cudaGetSymbolAddress((void**)&o, g_o);
    cudaGetSymbolAddress((void**)&x, g_x);
    cudaGetSymbolAddress((void**)&y, g_y);
    cudaGetSymbolAddress((void**)&f, g_f);

    const dim3 grid512(DMODEL / 128, (NNODES + 127) / 128);   // (4, 157)
    const dim3 gridff(DFFN / 128, (NNODES + 127) / 128);      // (16, 157)

    build_rowptr<<<(NNODES + 256) / 256, 256>>>(dst);

    gemm128<false, false><<<grid512, 256>>>(h, Wq, nullptr, q, NNODES, DMODEL, DMODEL);
    gemm128<false, false><<<grid512, 256>>>(h, Wk, nullptr, k, NNODES, DMODEL, DMODEL);
    gemm128<false, false><<<grid512, 256>>>(h, Wv, nullptr, v, NNODES, DMODEL, DMODEL);

    edge_scores<<<NEDGES / 8, 256>>>(src, dst);          // 8 warps/block, 1 warp/edge
    node_aggregate<<<NNODES, 128>>>(src);

    gemm128<false, false><<<grid512, 256>>>(a, Wo, nullptr, o, NNODES, DMODEL, DMODEL);
    residual_ln<<<NNODES, 128>>>(h, o, ln1g, ln1b, x);

    gemm128<true, true><<<gridff, 256>>>(x, W1, b1, f, NNODES, DFFN, DMODEL);
    gemm128<true, false><<<grid512, 256>>>(f, W2, b2, y, NNODES, DMODEL, DFFN);

    residual_ln<<<NNODES, 128>>>(x, y, ln2g, ln2b, out);
}

// round 4
// speedup vs baseline: 1.7630x; 1.7630x over previous
#include <cuda_runtime.h>
#include <cuda_bf16.h>
#include <math.h>
#include <cstdint>

#define NNODES 20000
#define NEDGES 640000
#define DMODEL 512
#define NHEAD 8
#define DFFN 2048

// ================= scratch (no allocs allowed) =================
__device__ __align__(256) float g_q[(size_t)NNODES * DMODEL];
__device__ __align__(256) float g_k[(size_t)NNODES * DMODEL];
__device__ __align__(256) float g_v[(size_t)NNODES * DMODEL];
__device__ __align__(256) float g_o[(size_t)NNODES * DMODEL];
__device__ __align__(256) float g_x[(size_t)NNODES * DMODEL];
__device__ __align__(256) float g_y[(size_t)NNODES * DMODEL];
__device__ __align__(256) float g_e[(size_t)NEDGES * NHEAD];
__device__ int   g_rowptr[NNODES + 1];

__device__ __align__(256) __nv_bfloat16 g_h_hi[(size_t)NNODES * DMODEL];
__device__ __align__(256) __nv_bfloat16 g_h_lo[(size_t)NNODES * DMODEL];
__device__ __align__(256) __nv_bfloat16 g_a_hi[(size_t)NNODES * DMODEL];
__device__ __align__(256) __nv_bfloat16 g_a_lo[(size_t)NNODES * DMODEL];
__device__ __align__(256) __nv_bfloat16 g_x_hi[(size_t)NNODES * DMODEL];
__device__ __align__(256) __nv_bfloat16 g_x_lo[(size_t)NNODES * DMODEL];
__device__ __align__(256) __nv_bfloat16 g_f_hi[(size_t)NNODES * DFFN];
__device__ __align__(256) __nv_bfloat16 g_f_lo[(size_t)NNODES * DFFN];

__device__ __align__(256) __nv_bfloat16 g_wqT_hi[DMODEL * DMODEL];
__device__ __align__(256) __nv_bfloat16 g_wqT_lo[DMODEL * DMODEL];
__device__ __align__(256) __nv_bfloat16 g_wkT_hi[DMODEL * DMODEL];
__device__ __align__(256) __nv_bfloat16 g_wkT_lo[DMODEL * DMODEL];
__device__ __align__(256) __nv_bfloat16 g_wvT_hi[DMODEL * DMODEL];
__device__ __align__(256) __nv_bfloat16 g_wvT_lo[DMODEL * DMODEL];
__device__ __align__(256) __nv_bfloat16 g_woT_hi[DMODEL * DMODEL];
__device__ __align__(256) __nv_bfloat16 g_woT_lo[DMODEL * DMODEL];
__device__ __align__(256) __nv_bfloat16 g_w1T_hi[DFFN * DMODEL];
__device__ __align__(256) __nv_bfloat16 g_w1T_lo[DFFN * DMODEL];
__device__ __align__(256) __nv_bfloat16 g_w2T_hi[DMODEL * DFFN];
__device__ __align__(256) __nv_bfloat16 g_w2T_lo[DMODEL * DFFN];

// ================= low-level helpers (base ISA only) =================
__device__ __forceinline__ uint32_t smem_to_u32(const void* p) {
    uint32_t a;
    asm("{ .reg .u64 t; cvta.to.shared.u64 t, %1; cvt.u32.u64 %0, t; }" : "=r"(a) : "l"(p));
    return a;
}
__device__ __forceinline__ void cp_async16(uint32_t saddr, const void* g) {
    asm volatile("cp.async.cg.shared.global [%0], [%1], 16;" :: "r"(saddr), "l"(g));
}
#define CP_COMMIT() asm volatile("cp.async.commit_group;" ::: "memory")
#define CP_WAIT1()  asm volatile("cp.async.wait_group 1;"  ::: "memory")

__device__ __forceinline__ void ldsm_x4(uint32_t addr, uint32_t& r0, uint32_t& r1,
                                        uint32_t& r2, uint32_t& r3) {
    asm volatile("ldmatrix.sync.aligned.m8n8.x4.shared.b16 {%0,%1,%2,%3}, [%4];"
                 : "=r"(r0), "=r"(r1), "=r"(r2), "=r"(r3) : "r"(addr));
}
__device__ __forceinline__ void mma_bf16(float c[4], const uint32_t a[4], const uint32_t b[2]) {
    asm volatile("mma.sync.aligned.m16n8k16.row.col.f32.bf16.bf16.f32 "
                 "{%0,%1,%2,%3}, {%4,%5,%6,%7}, {%8,%9}, {%0,%1,%2,%3};"
                 : "+f"(c[0]), "+f"(c[1]), "+f"(c[2]), "+f"(c[3])
                 : "r"(a[0]), "r"(a[1]), "r"(a[2]), "r"(a[3]), "r"(b[0]), "r"(b[1]));
}

// ================= CSR row pointers from sorted dst =================
__global__ void build_rowptr(const int* __restrict__ dst) {
    int i = blockIdx.x * blockDim.x + threadIdx.x;
    if (i > NNODES) return;
    int lo = 0, hi = NEDGES;
    while (lo < hi) { int mid = (lo + hi) >> 1; if (dst[mid] < i) lo = mid + 1; else hi = mid; }
    g_rowptr[i] = lo;
}

// ================= fp32 -> split bf16 =================
__global__ void split_f32(const float* __restrict__ x, __nv_bfloat16* __restrict__ hi,
                          __nv_bfloat16* __restrict__ lo, size_t n4) {
    size_t i = (size_t)blockIdx.x * blockDim.x + threadIdx.x;
    if (i >= n4) return;
    float4 v = ((const float4*)x)[i];
    __nv_bfloat16 h0 = __float2bfloat16(v.x), h1 = __float2bfloat16(v.y);
    __nv_bfloat16 h2 = __float2bfloat16(v.z), h3 = __float2bfloat16(v.w);
    hi[i * 4 + 0] = h0; hi[i * 4 + 1] = h1; hi[i * 4 + 2] = h2; hi[i * 4 + 3] = h3;
    lo[i * 4 + 0] = __float2bfloat16(v.x - __bfloat162float(h0));
    lo[i * 4 + 1] = __float2bfloat16(v.y - __bfloat162float(h1));
    lo[i * 4 + 2] = __float2bfloat16(v.z - __bfloat162float(h2));
    lo[i * 4 + 3] = __float2bfloat16(v.w - __bfloat162float(h3));
}

// ================= W[K,N] -> T[N,K] split bf16 (tiled transpose) =================
__global__ void transpose_split(const float* __restrict__ W, __nv_bfloat16* __restrict__ Thi,
                                __nv_bfloat16* __restrict__ Tlo, int K, int N) {
    __shared__ float t[32][33];
    int n0 = blockIdx.x * 32, k0 = blockIdx.y * 32;
    int tx = threadIdx.x, ty = threadIdx.y;  // 32 x 8
#pragma unroll
    for (int j = 0; j < 32; j += 8)
        t[ty + j][tx] = W[(size_t)(k0 + ty + j) * N + n0 + tx];
    __syncthreads();
#pragma unroll
    for (int j = 0; j < 32; j += 8) {
        int n = n0 + ty + j, k = k0 + tx;
        float v = t[tx][ty + j];
        __nv_bfloat16 h = __float2bfloat16(v);
        Thi[(size_t)n * K + k] = h;
        Tlo[(size_t)n * K + k] = __float2bfloat16(v - __bfloat162float(h));
    }
}

// ================= split-bf16 tensor-core GEMM (mma.sync, base ISA) =================
// C[M,N] = A[M,K] @ BT[N,K]^T ; A/BT as bf16 hi/lo ; fp32 accumulation.
// Tile 128x128x32, 8 warps (warp tile 32Mx64N), 3-stage cp.async pipeline.
// SMEM per stage: Ahi/Alo/Bhi/Blo each 8KB as 16B chunks indexed [kc(0..3)][row(0..127)].
#define STAGES 3
#define STAGE_BYTES 32768
#define GEMM_SMEM (STAGES * STAGE_BYTES)   // 96 KB

template<bool BIAS, bool RELU, bool OUTF32, bool OUTBF16>
__global__ __launch_bounds__(256, 1)
void gemm_mma(const __nv_bfloat16* __restrict__ Ahi, const __nv_bfloat16* __restrict__ Alo,
              const __nv_bfloat16* __restrict__ BThi, const __nv_bfloat16* __restrict__ BTlo,
              const float* __restrict__ bias,
              float* __restrict__ C, __nv_bfloat16* __restrict__ Chi, __nv_bfloat16* __restrict__ Clo,
              int M, int N, int K)
{
    extern __shared__ char smem[];
    const uint32_t sb = smem_to_u32(smem);
    const int tid = threadIdx.x, wid = tid >> 5, lid = tid & 31;
    const int wm = wid & 3, wn = wid >> 2;          // 4 x 2 warp grid
    const int row0 = blockIdx.y * 128, col0 = blockIdx.x * 128;

    float c[2][8][4];
#pragma unroll
    for (int mi = 0; mi < 2; mi++)
#pragma unroll
        for (int ni = 0; ni < 8; ni++)
#pragma unroll
            for (int e = 0; e < 4; e++) c[mi][ni][e] = 0.f;

    // ---- stage loader: 512 chunks per array, 2 per thread per array ----
    auto load_stage = [&](int s, int k0) {
        const uint32_t base = sb + s * STAGE_BYTES;
#pragma unroll
        for (int u = 0; u < 2; u++) {
            int i = tid + u * 256;
            int r = i >> 2, kc = i & 3;
            int gr = row0 + r;  if (gr >= M) gr = M - 1;   // clamp: rows>=M never stored
            const uint32_t da = base + (uint32_t)((kc * 128 + r) * 16);
            const size_t aoff = (size_t)gr * K + k0 + kc * 8;
            cp_async16(da,          Ahi + aoff);
            cp_async16(da + 8192,   Alo + aoff);
            const size_t boff = (size_t)(col0 + r) * K + k0 + kc * 8;
            cp_async16(da + 16384,  BThi + boff);
            cp_async16(da + 24576,  BTlo + boff);
        }
    };

    // ---- compute one 32-deep K slab from stage s ----
    auto compute_stage = [&](int s) {
        const uint32_t base = sb + s * STAGE_BYTES;
        const int lrow = lid & 7;
        const int lsel = lid >> 3;                 // ldmatrix matrix id 0..3
        const int a_madd  = ((lsel & 1) << 3) + lrow;   // A: mats (m0,k0)(m8,k0)(m0,k8)(m8,k8)
        const int a_kcadd = lsel >> 1;
        const int b_nadd  = ((lsel >> 1) << 3) + lrow;  // B: mats (n0,k0)(n0,k8)(n8,k0)(n8,k8)
        const int b_kcadd = lsel & 1;
#pragma unroll
        for (int ks = 0; ks < 2; ks++) {
            uint32_t ah[2][4], al[2][4];
#pragma unroll
            for (int mi = 0; mi < 2; mi++) {
                int m = wm * 32 + mi * 16 + a_madd;
                int kc = ks * 2 + a_kcadd;
                uint32_t ad = base + (uint32_t)((kc * 128 + m) * 16);
                ldsm_x4(ad,        ah[mi][0], ah[mi][1], ah[mi][2], ah[mi][3]);
                ldsm_x4(ad + 8192, al[mi][0], al[mi][1], al[mi][2], al[mi][3]);
            }
            uint32_t bh[8][2], bl[8][2];
#pragma unroll
            for (int nq = 0; nq < 4; nq++) {
                int n = wn * 64 + nq * 16 + b_nadd;
                int kc = ks * 2 + b_kcadd;
                uint32_t bd = base + 16384 + (uint32_t)((kc * 128 + n) * 16);
                ldsm_x4(bd,        bh[nq*2][0], bh[nq*2][1], bh[nq*2+1][0], bh[nq*2+1][1]);
                ldsm_x4(bd + 8192, bl[nq*2][0], bl[nq*2][1], bl[nq*2+1][0], bl[nq*2+1][1]);
            }
#pragma unroll
            for (int mi = 0; mi < 2; mi++)
#pragma unroll
                for (int ni = 0; ni < 8; ni++) {
                    mma_bf16(c[mi][ni], ah[mi], bh[ni]);
                    mma_bf16(c[mi][ni], ah[mi], bl[ni]);
                    mma_bf16(c[mi][ni], al[mi], bh[ni]);
                }
        }
    };

    const int nk = K >> 5;
#pragma unroll
    for (int s = 0; s < STAGES - 1; s++) { load_stage(s, s * 32); CP_COMMIT(); }

    for (int it = 0; it < nk; it++) {
        CP_WAIT1();
        __syncthreads();
        compute_stage(it % STAGES);
        int nxt = it + STAGES - 1;
        if (nxt < nk) load_stage(nxt % STAGES, nxt * 32);
        CP_COMMIT();
    }

    // ---- epilogue ----
    const int r_in = lid >> 2;
    const int c_in = (lid & 3) * 2;
#pragma unroll
    for (int mi = 0; mi < 2; mi++) {
#pragma unroll
        for (int half = 0; half < 2; half++) {
            int gr = row0 + wm * 32 + mi * 16 + half * 8 + r_in;
            if (gr >= M) continue;
#pragma unroll
            for (int ni = 0; ni < 8; ni++) {
                int gc = col0 + wn * 64 + ni * 8 + c_in;
                float v0 = c[mi][ni][half * 2 + 0];
                float v1 = c[mi][ni][half * 2 + 1];
                if (BIAS) { v0 += bias[gc]; v1 += bias[gc + 1]; }
                if (RELU) { v0 = fmaxf(v0, 0.f); v1 = fmaxf(v1, 0.f); }
                if (OUTF32)
                    *(float2*)(C + (size_t)gr * N + gc) = make_float2(v0, v1);
                if (OUTBF16) {
                    __nv_bfloat16 h0 = __float2bfloat16(v0);
                    __nv_bfloat16 h1 = __float2bfloat16(v1);
                    __nv_bfloat162 hh; hh.x = h0; hh.y = h1;
                    __nv_bfloat162 ll;
                    ll.x = __float2bfloat16(v0 - __bfloat162float(h0));
                    ll.y = __float2bfloat16(v1 - __bfloat162float(h1));
                    *(__nv_bfloat162*)(Chi + (size_t)gr * N + gc) = hh;
                    *(__nv_bfloat162*)(Clo + (size_t)gr * N + gc) = ll;
                }
            }
        }
    }
}

// ================= edge scores =================
__device__ __forceinline__ float dot4(float4 a, float4 b) {
    return a.x * b.x + a.y * b.y + a.z * b.z + a.w * b.w;
}
__global__ __launch_bounds__(256)
void edge_scores(const int* __restrict__ src, const int* __restrict__ dst) {
    int e = (int)((blockIdx.x * blockDim.x + threadIdx.x) >> 5);
    int lane = threadIdx.x & 31;
    if (e >= NEDGES) return;
    const float4* kk = (const float4*)(g_k + (size_t)src[e] * DMODEL);
    const float4* qq = (const float4*)(g_q + (size_t)dst[e] * DMODEL);
    float p0 = dot4(kk[lane +  0], qq[lane +  0]);
    float p1 = dot4(kk[lane + 32], qq[lane + 32]);
    float p2 = dot4(kk[lane + 64], qq[lane + 64]);
    float p3 = dot4(kk[lane + 96], qq[lane + 96]);
#pragma unroll
    for (int off = 8; off; off >>= 1) {
        p0 += __shfl_xor_sync(0xffffffffu, p0, off);
        p1 += __shfl_xor_sync(0xffffffffu, p1, off);
        p2 += __shfl_xor_sync(0xffffffffu, p2, off);
        p3 += __shfl_xor_sync(0xffffffffu, p3, off);
    }
    if ((lane & 15) == 0) {
        int h0 = lane >> 4;
        float* out = g_e + (size_t)e * NHEAD;
        out[h0 + 0] = p0 * 0.125f;
        out[h0 + 2] = p1 * 0.125f;
        out[h0 + 4] = p2 * 0.125f;
        out[h0 + 6] = p3 * 0.125f;
    }
}

// ================= per-node softmax + aggregation (emits bf16 hi/lo) =================
__global__ __launch_bounds__(128)
void node_aggregate(const int* __restrict__ src) {
    int node = blockIdx.x;
    int t = threadIdx.x;
    int beg = g_rowptr[node], end = g_rowptr[node + 1];

    __shared__ float s_m[NHEAD], s_rz[NHEAD];
    int head = t >> 4, sub = t & 15;
    float mx = -INFINITY;
    for (int e = beg + sub; e < end; e += 16)
        mx = fmaxf(mx, g_e[(size_t)e * NHEAD + head]);
#pragma unroll
    for (int off = 8; off; off >>= 1)
        mx = fmaxf(mx, __shfl_xor_sync(0xffffffffu, mx, off));
    float sum = 0.f;
    for (int e = beg + sub; e < end; e += 16)
        sum += __expf(g_e[(size_t)e * NHEAD + head] - mx);
#pragma unroll
    for (int off = 8; off; off >>= 1)
        sum += __shfl_xor_sync(0xffffffffu, sum, off);
    if (sub == 0) { s_m[head] = mx; s_rz[head] = (end > beg) ? (1.f / sum) : 0.f; }
    __syncthreads();

    int col = t << 2, h2 = t >> 4;
    float m = s_m[h2], rz = s_rz[h2];
    float4 acc = make_float4(0.f, 0.f, 0.f, 0.f);
    for (int e = beg; e < end; e++) {
        float w = __expf(g_e[(size_t)e * NHEAD + h2] - m) * rz;
        float4 vv = *(const float4*)(g_v + (size_t)src[e] * DMODEL + col);
        acc.x = fmaf(w, vv.x, acc.x);
        acc.y = fmaf(w, vv.y, acc.y);
        acc.z = fmaf(w, vv.z, acc.z);
        acc.w = fmaf(w, vv.w, acc.w);
    }
    __nv_bfloat16* ph = g_a_hi + (size_t)node * DMODEL + col;
    __nv_bfloat16* pl = g_a_lo + (size_t)node * DMODEL + col;
    float vv4[4] = {acc.x, acc.y, acc.z, acc.w};
#pragma unroll
    for (int i = 0; i < 4; i++) {
        __nv_bfloat16 h = __float2bfloat16(vv4[i]);
        ph[i] = h;
        pl[i] = __float2bfloat16(vv4[i] - __bfloat162float(h));
    }
}

// ================= residual + layernorm =================
template<bool EMIT_BF16>
__global__ __launch_bounds__(128)
void residual_ln(const float* __restrict__ A, const float* __restrict__ B,
                 const float* __restrict__ gamma, const float* __restrict__ beta,
                 float* __restrict__ out, __nv_bfloat16* __restrict__ ohi,
                 __nv_bfloat16* __restrict__ olo)
{
    int row = blockIdx.x;
    int t = threadIdx.x;
    float4 va = ((const float4*)(A + (size_t)row * DMODEL))[t];
    float4 vb = ((const float4*)(B + (size_t)row * DMODEL))[t];
    float4 v = make_float4(va.x + vb.x, va.y + vb.y, va.z + vb.z, va.w + vb.w);

    __shared__ float sh1[4], sh2[4];
    float s = v.x + v.y + v.z + v.w;
#pragma unroll
    for (int off = 16; off; off >>= 1) s += __shfl_xor_sync(0xffffffffu, s, off);
    if ((t & 31) == 0) sh1[t >> 5] = s;
    __syncthreads();
    float mu = (sh1[0] + sh1[1] + sh1[2] + sh1[3]) * (1.f / DMODEL);

    float dx = v.x - mu, dy = v.y - mu, dz = v.z - mu, dw = v.w - mu;
    float ss = dx * dx + dy * dy + dz * dz + dw * dw;
#pragma unroll
    for (int off = 16; off; off >>= 1) ss += __shfl_xor_sync(0xffffffffu, ss, off);
    if ((t & 31) == 0) sh2[t >> 5] = ss;
    __syncthreads();
    float var = (sh2[0] + sh2[1] + sh2[2] + sh2[3]) * (1.f / DMODEL);
    float rstd = rsqrtf(var + 1e-5f);

    float4 g = ((const float4*)gamma)[t];
    float4 be = ((const float4*)beta)[t];
    float o0 = dx * rstd * g.x + be.x;
    float o1 = dy * rstd * g.y + be.y;
    float o2 = dz * rstd * g.z + be.z;
    float o3 = dw * rstd * g.w + be.w;
    ((float4*)(out + (size_t)row * DMODEL))[t] = make_float4(o0, o1, o2, o3);
    if (EMIT_BF16) {
        __nv_bfloat16* ph = ohi + (size_t)row * DMODEL + t * 4;
        __nv_bfloat16* pl = olo + (size_t)row * DMODEL + t * 4;
        float ov[4] = {o0, o1, o2, o3};
#pragma unroll
        for (int i = 0; i < 4; i++) {
            __nv_bfloat16 h = __float2bfloat16(ov[i]);
            ph[i] = h;
            pl[i] = __float2bfloat16(ov[i] - __bfloat162float(h));
        }
    }
}

// ================= launch =================
extern "C" void kernel_launch(void* const* d_in, const int* in_sizes, int n_in,
                              void* d_out, int out_size)
{
    const float* h    = (const float*)d_in[0];
    const int*   src  = (const int*)d_in[1];
    const int*   dst  = (const int*)d_in[2];
    const float* Wq   = (const float*)d_in[3];
    const float* Wk   = (const float*)d_in[4];
    const float* Wv   = (const float*)d_in[5];
    const float* Wo   = (const float*)d_in[6];
    const float* ln1g = (const float*)d_in[7];
    const float* ln1b = (const float*)d_in[8];
    const float* ln2g = (const float*)d_in[9];
    const float* ln2b = (const float*)d_in[10];
    const float* W1   = (const float*)d_in[11];
    const float* b1   = (const float*)d_in[12];
    const float* W2   = (const float*)d_in[13];
    const float* b2   = (const float*)d_in[14];
    float* out = (float*)d_out;

    float *q, *k, *v, *o, *x, *y;
    cudaGetSymbolAddress((void**)&q, g_q);
    cudaGetSymbolAddress((void**)&k, g_k);
    cudaGetSymbolAddress((void**)&v, g_v);
    cudaGetSymbolAddress((void**)&o, g_o);
    cudaGetSymbolAddress((void**)&x, g_x);
    cudaGetSymbolAddress((void**)&y, g_y);
    __nv_bfloat16 *hhi, *hlo, *ahi, *alo, *xhi, *xlo, *fhi, *flo;
    cudaGetSymbolAddress((void**)&hhi, g_h_hi); cudaGetSymbolAddress((void**)&hlo, g_h_lo);
    cudaGetSymbolAddress((void**)&ahi, g_a_hi); cudaGetSymbolAddress((void**)&alo, g_a_lo);
    cudaGetSymbolAddress((void**)&xhi, g_x_hi); cudaGetSymbolAddress((void**)&xlo, g_x_lo);
    cudaGetSymbolAddress((void**)&fhi, g_f_hi); cudaGetSymbolAddress((void**)&flo, g_f_lo);
    __nv_bfloat16 *wqh, *wql, *wkh, *wkl, *wvh, *wvl, *woh, *wol, *w1h, *w1l, *w2h, *w2l;
    cudaGetSymbolAddress((void**)&wqh, g_wqT_hi); cudaGetSymbolAddress((void**)&wql, g_wqT_lo);
    cudaGetSymbolAddress((void**)&wkh, g_wkT_hi); cudaGetSymbolAddress((void**)&wkl, g_wkT_lo);
    cudaGetSymbolAddress((void**)&wvh, g_wvT_hi); cudaGetSymbolAddress((void**)&wvl, g_wvT_lo);
    cudaGetSymbolAddress((void**)&woh, g_woT_hi); cudaGetSymbolAddress((void**)&wol, g_woT_lo);
    cudaGetSymbolAddress((void**)&w1h, g_w1T_hi); cudaGetSymbolAddress((void**)&w1l, g_w1T_lo);
    cudaGetSymbolAddress((void**)&w2h, g_w2T_hi); cudaGetSymbolAddress((void**)&w2l, g_w2T_lo);

    cudaFuncSetAttribute(gemm_mma<false, false, true,  false>,
                         cudaFuncAttributeMaxDynamicSharedMemorySize, GEMM_SMEM);
    cudaFuncSetAttribute(gemm_mma<true,  true,  false, true>,
                         cudaFuncAttributeMaxDynamicSharedMemorySize, GEMM_SMEM);
    cudaFuncSetAttribute(gemm_mma<true,  false, true,  false>,
                         cudaFuncAttributeMaxDynamicSharedMemorySize, GEMM_SMEM);

    const int MB = (NNODES + 127) / 128;           // 157
    const dim3 g512(DMODEL / 128, MB);             // (4, 157)
    const dim3 gff(DFFN / 128, MB);                // (16, 157)

    build_rowptr<<<(NNODES + 256) / 256, 256>>>(dst);
    split_f32<<<(NNODES * DMODEL / 4 + 255) / 256, 256>>>(h, hhi, hlo, (size_t)NNODES * DMODEL / 4);

    transpose_split<<<dim3(DMODEL / 32, DMODEL / 32), dim3(32, 8)>>>(Wq, wqh, wql, DMODEL, DMODEL);
    transpose_split<<<dim3(DMODEL / 32, DMODEL / 32), dim3(32, 8)>>>(Wk, wkh, wkl, DMODEL, DMODEL);
    transpose_split<<<dim3(DMODEL / 32, DMODEL / 32), dim3(32, 8)>>>(Wv, wvh, wvl, DMODEL, DMODEL);
    transpose_split<<<dim3(DMODEL / 32, DMODEL / 32), dim3(32, 8)>>>(Wo, woh, wol, DMODEL, DMODEL);
    transpose_split<<<dim3(DFFN / 32, DMODEL / 32), dim3(32, 8)>>>(W1, w1h, w1l, DMODEL, DFFN);
    transpose_split<<<dim3(DMODEL / 32, DFFN / 32), dim3(32, 8)>>>(W2, w2h, w2l, DFFN, DMODEL);

    gemm_mma<false, false, true, false><<<g512, 256, GEMM_SMEM>>>(
        hhi, hlo, wqh, wql, nullptr, q, nullptr, nullptr, NNODES, DMODEL, DMODEL);
    gemm_mma<false, false, true, false><<<g512, 256, GEMM_SMEM>>>(
        hhi, hlo, wkh, wkl, nullptr, k, nullptr, nullptr, NNODES, DMODEL, DMODEL);
    gemm_mma<false, false, true, false><<<g512, 256, GEMM_SMEM>>>(
        hhi, hlo, wvh, wvl, nullptr, v, nullptr, nullptr, NNODES, DMODEL, DMODEL);

    edge_scores<<<NEDGES / 8, 256>>>(src, dst);
    node_aggregate<<<NNODES, 128>>>(src);

    gemm_mma<false, false, true, false><<<g512, 256, GEMM_SMEM>>>(
        ahi, alo, woh, wol, nullptr, o, nullptr, nullptr, NNODES, DMODEL, DMODEL);
    residual_ln<true><<<NNODES, 128>>>(h, o, ln1g, ln1b, x, xhi, xlo);

    gemm_mma<true, true, false, true><<<gff, 256, GEMM_SMEM>>>(
        xhi, xlo, w1h, w1l, b1, nullptr, fhi, flo, NNODES, DFFN, DMODEL);
    gemm_mma<true, false, true, false><<<g512, 256, GEMM_SMEM>>>(
        fhi, flo, w2h, w2l, b2, y, nullptr, nullptr, NNODES, DMODEL, DFFN);

    residual_ln<false><<<NNODES, 128>>>(x, y, ln2g, ln2b, out, nullptr, nullptr);
}

// round 5
// speedup vs baseline: 2.6414x; 1.4982x over previous
#include <cuda_runtime.h>
#include <cuda_fp16.h>
#include <math.h>
#include <cstdint>

#define NNODES 20000
#define NEDGES 640000
#define DMODEL 512
#define NHEAD 8
#define DFFN 2048

// ================= scratch (no allocs allowed) =================
__device__ __align__(256) float g_q[(size_t)NNODES * DMODEL];
__device__ __align__(256) float g_k[(size_t)NNODES * DMODEL];
__device__ __align__(256) float g_v[(size_t)NNODES * DMODEL];
__device__ __align__(256) float g_o[(size_t)NNODES * DMODEL];
__device__ __align__(256) float g_x[(size_t)NNODES * DMODEL];
__device__ __align__(256) float g_y[(size_t)NNODES * DMODEL];
__device__ __align__(256) float g_e[(size_t)NEDGES * NHEAD];
__device__ int   g_rowptr[NNODES + 1];

// A-side activations: single fp16
__device__ __align__(256) __half g_h_h[(size_t)NNODES * DMODEL];
__device__ __align__(256) __half g_a_h[(size_t)NNODES * DMODEL];
__device__ __align__(256) __half g_x_h[(size_t)NNODES * DMODEL];
__device__ __align__(256) __half g_f_h[(size_t)NNODES * DFFN];

// B-side weights (transposed [N,K]): fp16 hi + lo
__device__ __align__(256) __half g_wqT_hi[DMODEL * DMODEL];
__device__ __align__(256) __half g_wqT_lo[DMODEL * DMODEL];
__device__ __align__(256) __half g_wkT_hi[DMODEL * DMODEL];
__device__ __align__(256) __half g_wkT_lo[DMODEL * DMODEL];
__device__ __align__(256) __half g_wvT_hi[DMODEL * DMODEL];
__device__ __align__(256) __half g_wvT_lo[DMODEL * DMODEL];
__device__ __align__(256) __half g_woT_hi[DMODEL * DMODEL];
__device__ __align__(256) __half g_woT_lo[DMODEL * DMODEL];
__device__ __align__(256) __half g_w1T_hi[DFFN * DMODEL];
__device__ __align__(256) __half g_w1T_lo[DFFN * DMODEL];
__device__ __align__(256) __half g_w2T_hi[DMODEL * DFFN];
__device__ __align__(256) __half g_w2T_lo[DMODEL * DFFN];

// ================= low-level helpers (base ISA only) =================
__device__ __forceinline__ uint32_t smem_to_u32(const void* p) {
    uint32_t a;
    asm("{ .reg .u64 t; cvta.to.shared.u64 t, %1; cvt.u32.u64 %0, t; }" : "=r"(a) : "l"(p));
    return a;
}
__device__ __forceinline__ void cp_async16(uint32_t saddr, const void* g) {
    asm volatile("cp.async.cg.shared.global [%0], [%1], 16;" :: "r"(saddr), "l"(g));
}
#define CP_COMMIT() asm volatile("cp.async.commit_group;" ::: "memory")
#define CP_WAIT1()  asm volatile("cp.async.wait_group 1;"  ::: "memory")

__device__ __forceinline__ void ldsm_x4(uint32_t addr, uint32_t& r0, uint32_t& r1,
                                        uint32_t& r2, uint32_t& r3) {
    asm volatile("ldmatrix.sync.aligned.m8n8.x4.shared.b16 {%0,%1,%2,%3}, [%4];"
                 : "=r"(r0), "=r"(r1), "=r"(r2), "=r"(r3) : "r"(addr));
}
__device__ __forceinline__ void mma_f16(float c[4], const uint32_t a[4], const uint32_t b[2]) {
    asm volatile("mma.sync.aligned.m16n8k16.row.col.f32.f16.f16.f32 "
                 "{%0,%1,%2,%3}, {%4,%5,%6,%7}, {%8,%9}, {%0,%1,%2,%3};"
                 : "+f"(c[0]), "+f"(c[1]), "+f"(c[2]), "+f"(c[3])
                 : "r"(a[0]), "r"(a[1]), "r"(a[2]), "r"(a[3]), "r"(b[0]), "r"(b[1]));
}

// ================= CSR row pointers from sorted dst =================
__global__ void build_rowptr(const int* __restrict__ dst) {
    int i = blockIdx.x * blockDim.x + threadIdx.x;
    if (i > NNODES) return;
    int lo = 0, hi = NEDGES;
    while (lo < hi) { int mid = (lo + hi) >> 1; if (dst[mid] < i) lo = mid + 1; else hi = mid; }
    g_rowptr[i] = lo;
}

// ================= fp32 -> fp16 cast (A-side) =================
__global__ void cast_f16(const float* __restrict__ x, __half* __restrict__ h, size_t n4) {
    size_t i = (size_t)blockIdx.x * blockDim.x + threadIdx.x;
    if (i >= n4) return;
    float4 v = ((const float4*)x)[i];
    __half2 a; a.x = __float2half_rn(v.x); a.y = __float2half_rn(v.y);
    __half2 b; b.x = __float2half_rn(v.z); b.y = __float2half_rn(v.w);
    ((__half2*)h)[i * 2 + 0] = a;
    ((__half2*)h)[i * 2 + 1] = b;
}

// ================= W[K,N] -> T[N,K] fp16 hi/lo (tiled transpose) =================
__global__ void transpose_split(const float* __restrict__ W, __half* __restrict__ Thi,
                                __half* __restrict__ Tlo, int K, int N) {
    __shared__ float t[32][33];
    int n0 = blockIdx.x * 32, k0 = blockIdx.y * 32;
    int tx = threadIdx.x, ty = threadIdx.y;  // 32 x 8
#pragma unroll
    for (int j = 0; j < 32; j += 8)
        t[ty + j][tx] = W[(size_t)(k0 + ty + j) * N + n0 + tx];
    __syncthreads();
#pragma unroll
    for (int j = 0; j < 32; j += 8) {
        int n = n0 + ty + j, k = k0 + tx;
        float v = t[tx][ty + j];
        __half h = __float2half_rn(v);
        Thi[(size_t)n * K + k] = h;
        Tlo[(size_t)n * K + k] = __float2half_rn(v - __half2float(h));
    }
}

// ================= fp16 2-product tensor-core GEMM =================
// C[M,N] = A[M,K] @ BT[N,K]^T ; A single fp16, BT fp16 hi+lo ; fp32 accumulation.
// C = A*Bhi + A*Blo. CTA tile 256x128x32, 8 warps (warp tile 64x64), 3-stage cp.async.
// Stage layout (32KB): A 16KB [(kc*256+r)*16], Bhi 8KB @16384 [(kc*128+n)*16], Blo 8KB @24576.
#define STAGES 3
#define STAGE_BYTES 32768
#define GEMM_SMEM (STAGES * STAGE_BYTES)   // 96 KB

template<bool BIAS, bool RELU, bool OUTF32, bool OUTF16>
__global__ __launch_bounds__(256, 1)
void gemm_mma(const __half* __restrict__ A,
              const __half* __restrict__ BThi, const __half* __restrict__ BTlo,
              const float* __restrict__ bias,
              float* __restrict__ C, __half* __restrict__ Ch,
              int M, int N, int K)
{
    extern __shared__ char smem[];
    const uint32_t sb = smem_to_u32(smem);
    const int tid = threadIdx.x, wid = tid >> 5, lid = tid & 31;
    const int wm = wid & 3, wn = wid >> 2;          // 4 (M) x 2 (N) warp grid
    const int row0 = blockIdx.y * 256, col0 = blockIdx.x * 128;

    float c[4][8][4];
#pragma unroll
    for (int mi = 0; mi < 4; mi++)
#pragma unroll
        for (int ni = 0; ni < 8; ni++)
#pragma unroll
            for (int e = 0; e < 4; e++) c[mi][ni][e] = 0.f;

    // ---- stage loader: A 1024 chunks, Bhi/Blo 512 each; 8 cp.async per thread ----
    auto load_stage = [&](int s, int k0) {
        const uint32_t base = sb + s * STAGE_BYTES;
#pragma unroll
        for (int u = 0; u < 4; u++) {
            int i = tid + u * 256;
            int r = i >> 2, kc = i & 3;
            int gr = row0 + r;  if (gr >= M) gr = M - 1;   // clamp; rows >= M never stored
            cp_async16(base + (uint32_t)((kc * 256 + r) * 16),
                       A + (size_t)gr * K + k0 + kc * 8);
        }
#pragma unroll
        for (int u = 0; u < 2; u++) {
            int i = tid + u * 256;
            int r = i >> 2, kc = i & 3;
            const uint32_t db = base + 16384 + (uint32_t)((kc * 128 + r) * 16);
            const size_t boff = (size_t)(col0 + r) * K + k0 + kc * 8;
            cp_async16(db,        BThi + boff);
            cp_async16(db + 8192, BTlo + boff);
        }
    };

    // ---- compute one 32-deep K slab from stage s ----
    auto compute_stage = [&](int s) {
        const uint32_t base = sb + s * STAGE_BYTES;
        const int lrow = lid & 7;
        const int lsel = lid >> 3;
        const int a_madd  = ((lsel & 1) << 3) + lrow;   // A mats: (m0,k0)(m8,k0)(m0,k8)(m8,k8)
        const int a_kcadd = lsel >> 1;
        const int b_nadd  = ((lsel >> 1) << 3) + lrow;  // B mats: (n0,k0)(n0,k8)(n8,k0)(n8,k8)
        const int b_kcadd = lsel & 1;
        for (int ks = 0; ks < 2; ks++) {
            uint32_t ah[4][4];
#pragma unroll
            for (int mi = 0; mi < 4; mi++) {
                int m = wm * 64 + mi * 16 + a_madd;
                int kc = ks * 2 + a_kcadd;
                ldsm_x4(base + (uint32_t)((kc * 256 + m) * 16),
                        ah[mi][0], ah[mi][1], ah[mi][2], ah[mi][3]);
            }
            uint32_t bh[8][2], bl[8][2];
#pragma unroll
            for (int nq = 0; nq < 4; nq++) {
                int n = wn * 64 + nq * 16 + b_nadd;
                int kc = ks * 2 + b_kcadd;
                uint32_t bd = base + 16384 + (uint32_t)((kc * 128 + n) * 16);
                ldsm_x4(bd,        bh[nq*2][0], bh[nq*2][1], bh[nq*2+1][0], bh[nq*2+1][1]);
                ldsm_x4(bd + 8192, bl[nq*2][0], bl[nq*2][1], bl[nq*2+1][0], bl[nq*2+1][1]);
            }
#pragma unroll
            for (int mi = 0; mi < 4; mi++)
#pragma unroll
                for (int ni = 0; ni < 8; ni++) {
                    mma_f16(c[mi][ni], ah[mi], bh[ni]);
                    mma_f16(c[mi][ni], ah[mi], bl[ni]);
                }
        }
    };

    const int nk = K >> 5;
#pragma unroll
    for (int s = 0; s < STAGES - 1; s++) { load_stage(s, s * 32); CP_COMMIT(); }

    for (int it = 0; it < nk; it++) {
        CP_WAIT1();
        __syncthreads();
        compute_stage(it % STAGES);
        int nxt = it + STAGES - 1;
        if (nxt < nk) load_stage(nxt % STAGES, nxt * 32);
        CP_COMMIT();
    }

    // ---- epilogue ----
    const int r_in = lid >> 2;
    const int c_in = (lid & 3) * 2;
#pragma unroll
    for (int mi = 0; mi < 4; mi++) {
#pragma unroll
        for (int half = 0; half < 2; half++) {
            int gr = row0 + wm * 64 + mi * 16 + half * 8 + r_in;
            if (gr >= M) continue;
#pragma unroll
            for (int ni = 0; ni < 8; ni++) {
                int gc = col0 + wn * 64 + ni * 8 + c_in;
                float v0 = c[mi][ni][half * 2 + 0];
                float v1 = c[mi][ni][half * 2 + 1];
                if (BIAS) { v0 += bias[gc]; v1 += bias[gc + 1]; }
                if (RELU) { v0 = fmaxf(v0, 0.f); v1 = fmaxf(v1, 0.f); }
                if (OUTF32)
                    *(float2*)(C + (size_t)gr * N + gc) = make_float2(v0, v1);
                if (OUTF16) {
                    __half2 hh; hh.x = __float2half_rn(v0); hh.y = __float2half_rn(v1);
                    *(__half2*)(Ch + (size_t)gr * N + gc) = hh;
                }
            }
        }
    }
}

// ================= edge scores (CSR: q cached per node) =================
__device__ __forceinline__ float dot4(float4 a, float4 b) {
    return a.x * b.x + a.y * b.y + a.z * b.z + a.w * b.w;
}
__global__ __launch_bounds__(128)
void edge_scores_csr(const int* __restrict__ src) {
    int node = blockIdx.x;
    int t = threadIdx.x;
    int beg = g_rowptr[node], end = g_rowptr[node + 1];

    __shared__ float4 qs[128];
    qs[t] = ((const float4*)(g_q + (size_t)node * DMODEL))[t];
    __syncthreads();

    int w = t >> 5, lane = t & 31;
    for (int e = beg + w; e < end; e += 4) {
        const float4* kk = (const float4*)(g_k + (size_t)src[e] * DMODEL);
        float p0 = dot4(kk[lane +  0], qs[lane +  0]);
        float p1 = dot4(kk[lane + 32], qs[lane + 32]);
        float p2 = dot4(kk[lane + 64], qs[lane + 64]);
        float p3 = dot4(kk[lane + 96], qs[lane + 96]);
#pragma unroll
        for (int off = 8; off; off >>= 1) {
            p0 += __shfl_xor_sync(0xffffffffu, p0, off);
            p1 += __shfl_xor_sync(0xffffffffu, p1, off);
            p2 += __shfl_xor_sync(0xffffffffu, p2, off);
            p3 += __shfl_xor_sync(0xffffffffu, p3, off);
        }
        if ((lane & 15) == 0) {
            int h0 = lane >> 4;
            float* out = g_e + (size_t)e * NHEAD;
            out[h0 + 0] = p0 * 0.125f;
            out[h0 + 2] = p1 * 0.125f;
            out[h0 + 4] = p2 * 0.125f;
            out[h0 + 6] = p3 * 0.125f;
        }
    }
}

// ================= per-node softmax + aggregation (emits fp16) =================
__global__ __launch_bounds__(128)
void node_aggregate(const int* __restrict__ src) {
    int node = blockIdx.x;
    int t = threadIdx.x;
    int beg = g_rowptr[node], end = g_rowptr[node + 1];

    __shared__ float s_m[NHEAD], s_rz[NHEAD];
    int head = t >> 4, sub = t & 15;
    float mx = -INFINITY;
    for (int e = beg + sub; e < end; e += 16)
        mx = fmaxf(mx, g_e[(size_t)e * NHEAD + head]);
#pragma unroll
    for (int off = 8; off; off >>= 1)
        mx = fmaxf(mx, __shfl_xor_sync(0xffffffffu, mx, off));
    float sum = 0.f;
    for (int e = beg + sub; e < end; e += 16)
        sum += __expf(g_e[(size_t)e * NHEAD + head] - mx);
#pragma unroll
    for (int off = 8; off; off >>= 1)
        sum += __shfl_xor_sync(0xffffffffu, sum, off);
    if (sub == 0) { s_m[head] = mx; s_rz[head] = (end > beg) ? (1.f / sum) : 0.f; }
    __syncthreads();

    int col = t << 2, h2 = t >> 4;
    float m = s_m[h2], rz = s_rz[h2];
    float4 acc = make_float4(0.f, 0.f, 0.f, 0.f);
    for (int e = beg; e < end; e++) {
        float w = __expf(g_e[(size_t)e * NHEAD + h2] - m) * rz;
        float4 vv = *(const float4*)(g_v + (size_t)src[e] * DMODEL + col);
        acc.x = fmaf(w, vv.x, acc.x);
        acc.y = fmaf(w, vv.y, acc.y);
        acc.z = fmaf(w, vv.z, acc.z);
        acc.w = fmaf(w, vv.w, acc.w);
    }
    __half2 h01; h01.x = __float2half_rn(acc.x); h01.y = __float2half_rn(acc.y);
    __half2 h23; h23.x = __float2half_rn(acc.z); h23.y = __float2half_rn(acc.w);
    __half2* ph = (__half2*)(g_a_h + (size_t)node * DMODEL + col);
    ph[0] = h01; ph[1] = h23;
}

// ================= residual + layernorm =================
template<bool EMIT_F16>
__global__ __launch_bounds__(128)
void residual_ln(const float* __restrict__ A, const float* __restrict__ B,
                 const float* __restrict__ gamma, const float* __restrict__ beta,
                 float* __restrict__ out, __half* __restrict__ oh)
{
    int row = blockIdx.x;
    int t = threadIdx.x;
    float4 va = ((const float4*)(A + (size_t)row * DMODEL))[t];
    float4 vb = ((const float4*)(B + (size_t)row * DMODEL))[t];
    float4 v = make_float4(va.x + vb.x, va.y + vb.y, va.z + vb.z, va.w + vb.w);

    __shared__ float sh1[4], sh2[4];
    float s = v.x + v.y + v.z + v.w;
#pragma unroll
    for (int off = 16; off; off >>= 1) s += __shfl_xor_sync(0xffffffffu, s, off);
    if ((t & 31) == 0) sh1[t >> 5] = s;
    __syncthreads();
    float mu = (sh1[0] + sh1[1] + sh1[2] + sh1[3]) * (1.f / DMODEL);

    float dx = v.x - mu, dy = v.y - mu, dz = v.z - mu, dw = v.w - mu;
    float ss = dx * dx + dy * dy + dz * dz + dw * dw;
#pragma unroll
    for (int off = 16; off; off >>= 1) ss += __shfl_xor_sync(0xffffffffu, ss, off);
    if ((t & 31) == 0) sh2[t >> 5] = ss;
    __syncthreads();
    float var = (sh2[0] + sh2[1] + sh2[2] + sh2[3]) * (1.f / DMODEL);
    float rstd = rsqrtf(var + 1e-5f);

    float4 g = ((const float4*)gamma)[t];
    float4 be = ((const float4*)beta)[t];
    float o0 = dx * rstd * g.x + be.x;
    float o1 = dy * rstd * g.y + be.y;
    float o2 = dz * rstd * g.z + be.z;
    float o3 = dw * rstd * g.w + be.w;
    ((float4*)(out + (size_t)row * DMODEL))[t] = make_float4(o0, o1, o2, o3);
    if (EMIT_F16) {
        __half2 h01; h01.x = __float2half_rn(o0); h01.y = __float2half_rn(o1);
        __half2 h23; h23.x = __float2half_rn(o2); h23.y = __float2half_rn(o3);
        __half2* ph = (__half2*)(oh + (size_t)row * DMODEL + t * 4);
        ph[0] = h01; ph[1] = h23;
    }
}

// ================= launch =================
extern "C" void kernel_launch(void* const* d_in, const int* in_sizes, int n_in,
                              void* d_out, int out_size)
{
    const float* h    = (const float*)d_in[0];
    const int*   src  = (const int*)d_in[1];
    const int*   dst  = (const int*)d_in[2];
    const float* Wq   = (const float*)d_in[3];
    const float* Wk   = (const float*)d_in[4];
    const float* Wv   = (const float*)d_in[5];
    const float* Wo   = (const float*)d_in[6];
    const float* ln1g = (const float*)d_in[7];
    const float* ln1b = (const float*)d_in[8];
    const float* ln2g = (const float*)d_in[9];
    const float* ln2b = (const float*)d_in[10];
    const float* W1   = (const float*)d_in[11];
    const float* b1   = (const float*)d_in[12];
    const float* W2   = (const float*)d_in[13];
    const float* b2   = (const float*)d_in[14];
    float* out = (float*)d_out;

    float *q, *k, *v, *o, *x, *y;
    cudaGetSymbolAddress((void**)&q, g_q);
    cudaGetSymbolAddress((void**)&k, g_k);
    cudaGetSymbolAddress((void**)&v, g_v);
    cudaGetSymbolAddress((void**)&o, g_o);
    cudaGetSymbolAddress((void**)&x, g_x);
    cudaGetSymbolAddress((void**)&y, g_y);
    __half *hh, *ah, *xh, *fh;
    cudaGetSymbolAddress((void**)&hh, g_h_h);
    cudaGetSymbolAddress((void**)&ah, g_a_h);
    cudaGetSymbolAddress((void**)&xh, g_x_h);
    cudaGetSymbolAddress((void**)&fh, g_f_h);
    __half *wqh, *wql, *wkh, *wkl, *wvh, *wvl, *woh, *wol, *w1h, *w1l, *w2h, *w2l;
    cudaGetSymbolAddress((void**)&wqh, g_wqT_hi); cudaGetSymbolAddress((void**)&wql, g_wqT_lo);
    cudaGetSymbolAddress((void**)&wkh, g_wkT_hi); cudaGetSymbolAddress((void**)&wkl, g_wkT_lo);
    cudaGetSymbolAddress((void**)&wvh, g_wvT_hi); cudaGetSymbolAddress((void**)&wvl, g_wvT_lo);
    cudaGetSymbolAddress((void**)&woh, g_woT_hi); cudaGetSymbolAddress((void**)&wol, g_woT_lo);
    cudaGetSymbolAddress((void**)&w1h, g_w1T_hi); cudaGetSymbolAddress((void**)&w1l, g_w1T_lo);
    cudaGetSymbolAddress((void**)&w2h, g_w2T_hi); cudaGetSymbolAddress((void**)&w2l, g_w2T_lo);

    cudaFuncSetAttribute(gemm_mma<false, false, true,  false>,
                         cudaFuncAttributeMaxDynamicSharedMemorySize, GEMM_SMEM);
    cudaFuncSetAttribute(gemm_mma<true,  true,  false, true>,
                         cudaFuncAttributeMaxDynamicSharedMemorySize, GEMM_SMEM);
    cudaFuncSetAttribute(gemm_mma<true,  false, true,  false>,
                         cudaFuncAttributeMaxDynamicSharedMemorySize, GEMM_SMEM);

    const int MB = (NNODES + 255) / 256;           // 79
    const dim3 g512(DMODEL / 128, MB);             // (4, 79)
    const dim3 gff(DFFN / 128, MB);                // (16, 79)

    build_rowptr<<<(NNODES + 256) / 256, 256>>>(dst);
    cast_f16<<<(NNODES * DMODEL / 4 + 255) / 256, 256>>>(h, hh, (size_t)NNODES * DMODEL / 4);

    transpose_split<<<dim3(DMODEL / 32, DMODEL / 32), dim3(32, 8)>>>(Wq, wqh, wql, DMODEL, DMODEL);
    transpose_split<<<dim3(DMODEL / 32, DMODEL / 32), dim3(32, 8)>>>(Wk, wkh, wkl, DMODEL, DMODEL);
    transpose_split<<<dim3(DMODEL / 32, DMODEL / 32), dim3(32, 8)>>>(Wv, wvh, wvl, DMODEL, DMODEL);
    transpose_split<<<dim3(DMODEL / 32, DMODEL / 32), dim3(32, 8)>>>(Wo, woh, wol, DMODEL, DMODEL);
    transpose_split<<<dim3(DFFN / 32, DMODEL / 32), dim3(32, 8)>>>(W1, w1h, w1l, DMODEL, DFFN);
    transpose_split<<<dim3(DMODEL / 32, DFFN / 32), dim3(32, 8)>>>(W2, w2h, w2l, DFFN, DMODEL);

    gemm_mma<false, false, true, false><<<g512, 256, GEMM_SMEM>>>(
        hh, wqh, wql, nullptr, q, nullptr, NNODES, DMODEL, DMODEL);
    gemm_mma<false, false, true, false><<<g512, 256, GEMM_SMEM>>>(
        hh, wkh, wkl, nullptr, k, nullptr, NNODES, DMODEL, DMODEL);
    gemm_mma<false, false, true, false><<<g512, 256, GEMM_SMEM>>>(
        hh, wvh, wvl, nullptr, v, nullptr, NNODES, DMODEL, DMODEL);

    edge_scores_csr<<<NNODES, 128>>>(src);
    node_aggregate<<<NNODES, 128>>>(src);

    gemm_mma<false, false, true, false><<<g512, 256, GEMM_SMEM>>>(
        ah, woh, wol, nullptr, o, nullptr, NNODES, DMODEL, DMODEL);
    residual_ln<true><<<NNODES, 128>>>(h, o, ln1g, ln1b, x, xh);

    gemm_mma<true, true, false, true><<<gff, 256, GEMM_SMEM>>>(
        xh, w1h, w1l, b1, nullptr, fh, NNODES, DFFN, DMODEL);
    gemm_mma<true, false, true, false><<<g512, 256, GEMM_SMEM>>>(
        fh, w2h, w2l, b2, y, nullptr, NNODES, DMODEL, DFFN);

    residual_ln<false><<<NNODES, 128>>>(x, y, ln2g, ln2b, out, nullptr);
}

// round 6
// speedup vs baseline: 3.6683x; 1.3888x over previous
#include <cuda_runtime.h>
#include <cuda_fp16.h>
#include <math.h>
#include <cstdint>

#define NNODES 20000
#define NEDGES 640000
#define DMODEL 512
#define NHEAD 8
#define DFFN 2048
#define DQKV 1536

// ================= scratch (no allocs allowed) =================
__device__ __align__(256) float g_o[(size_t)NNODES * DMODEL];
__device__ __align__(256) float g_x[(size_t)NNODES * DMODEL];
__device__ __align__(256) float g_y[(size_t)NNODES * DMODEL];
__device__ __align__(256) float g_e[(size_t)NEDGES * NHEAD];
__device__ int   g_rowptr[NNODES + 1];

__device__ __align__(256) __half g_h_h[(size_t)NNODES * DMODEL];
__device__ __align__(256) __half g_qkv[(size_t)NNODES * DQKV];   // q | k | v  fp16
__device__ __align__(256) __half g_a_h[(size_t)NNODES * DMODEL];
__device__ __align__(256) __half g_x_h[(size_t)NNODES * DMODEL];
__device__ __align__(256) __half g_f_h[(size_t)NNODES * DFFN];

__device__ __align__(256) __half g_wqkvT[DQKV * DMODEL];         // [1536,512]
__device__ __align__(256) __half g_woT[DMODEL * DMODEL];
__device__ __align__(256) __half g_w1T[DFFN * DMODEL];
__device__ __align__(256) __half g_w2T[DMODEL * DFFN];

// ================= low-level helpers (base ISA only) =================
__device__ __forceinline__ uint32_t smem_to_u32(const void* p) {
    uint32_t a;
    asm("{ .reg .u64 t; cvta.to.shared.u64 t, %1; cvt.u32.u64 %0, t; }" : "=r"(a) : "l"(p));
    return a;
}
__device__ __forceinline__ void cp_async16(uint32_t saddr, const void* g) {
    asm volatile("cp.async.cg.shared.global [%0], [%1], 16;" :: "r"(saddr), "l"(g));
}
#define CP_COMMIT() asm volatile("cp.async.commit_group;" ::: "memory")
#define CP_WAIT1()  asm volatile("cp.async.wait_group 1;"  ::: "memory")

__device__ __forceinline__ void ldsm_x4(uint32_t addr, uint32_t& r0, uint32_t& r1,
                                        uint32_t& r2, uint32_t& r3) {
    asm volatile("ldmatrix.sync.aligned.m8n8.x4.shared.b16 {%0,%1,%2,%3}, [%4];"
                 : "=r"(r0), "=r"(r1), "=r"(r2), "=r"(r3) : "r"(addr));
}
__device__ __forceinline__ void mma_f16(float c[4], const uint32_t a[4], const uint32_t b[2]) {
    asm volatile("mma.sync.aligned.m16n8k16.row.col.f32.f16.f16.f32 "
                 "{%0,%1,%2,%3}, {%4,%5,%6,%7}, {%8,%9}, {%0,%1,%2,%3};"
                 : "+f"(c[0]), "+f"(c[1]), "+f"(c[2]), "+f"(c[3])
                 : "r"(a[0]), "r"(a[1]), "r"(a[2]), "r"(a[3]), "r"(b[0]), "r"(b[1]));
}

// ================= CSR row pointers from sorted dst =================
__global__ void build_rowptr(const int* __restrict__ dst) {
    int i = blockIdx.x * blockDim.x + threadIdx.x;
    if (i > NNODES) return;
    int lo = 0, hi = NEDGES;
    while (lo < hi) { int mid = (lo + hi) >> 1; if (dst[mid] < i) lo = mid + 1; else hi = mid; }
    g_rowptr[i] = lo;
}

// ================= fp32 -> fp16 cast =================
__global__ void cast_f16(const float* __restrict__ x, __half* __restrict__ h, size_t n4) {
    size_t i = (size_t)blockIdx.x * blockDim.x + threadIdx.x;
    if (i >= n4) return;
    float4 v = ((const float4*)x)[i];
    __half2 a; a.x = __float2half_rn(v.x); a.y = __float2half_rn(v.y);
    __half2 b; b.x = __float2half_rn(v.z); b.y = __float2half_rn(v.w);
    ((__half2*)h)[i * 2 + 0] = a;
    ((__half2*)h)[i * 2 + 1] = b;
}

// ================= W[K,N] -> T[N,K] fp16 (tiled transpose+cast) =================
__global__ void transpose_cast(const float* __restrict__ W, __half* __restrict__ T,
                               int K, int N) {
    __shared__ float t[32][33];
    int n0 = blockIdx.x * 32, k0 = blockIdx.y * 32;
    int tx = threadIdx.x, ty = threadIdx.y;  // 32 x 8
#pragma unroll
    for (int j = 0; j < 32; j += 8)
        t[ty + j][tx] = W[(size_t)(k0 + ty + j) * N + n0 + tx];
    __syncthreads();
#pragma unroll
    for (int j = 0; j < 32; j += 8)
        T[(size_t)(n0 + ty + j) * K + k0 + tx] = __float2half_rn(t[tx][ty + j]);
}

// ================= fp16 tensor-core GEMM (single product) =================
// C[M,N] = A[M,K] @ BT[N,K]^T ; fp32 accumulation.
// CTA tile 256x128x32, 8 warps (warp tile 64x64), 3-stage cp.async.
// Stage (24KB): A 16KB [(kc*256+r)*16], B 8KB @16384 [(kc*128+n)*16].
#define STAGES 3
#define STAGE_BYTES 24576
#define GEMM_SMEM (STAGES * STAGE_BYTES)   // 72 KB

template<bool BIAS, bool RELU, bool OUTF32, bool OUTF16>
__global__ __launch_bounds__(256, 1)
void gemm_mma(const __half* __restrict__ A, const __half* __restrict__ BT,
              const float* __restrict__ bias,
              float* __restrict__ C, __half* __restrict__ Ch,
              int M, int N, int K)
{
    extern __shared__ char smem[];
    const uint32_t sb = smem_to_u32(smem);
    const int tid = threadIdx.x, wid = tid >> 5, lid = tid & 31;
    const int wm = wid & 3, wn = wid >> 2;          // 4 (M) x 2 (N) warp grid
    const int row0 = blockIdx.y * 256, col0 = blockIdx.x * 128;

    float c[4][8][4];
#pragma unroll
    for (int mi = 0; mi < 4; mi++)
#pragma unroll
        for (int ni = 0; ni < 8; ni++)
#pragma unroll
            for (int e = 0; e < 4; e++) c[mi][ni][e] = 0.f;

    auto load_stage = [&](int s, int k0) {
        const uint32_t base = sb + s * STAGE_BYTES;
#pragma unroll
        for (int u = 0; u < 4; u++) {
            int i = tid + u * 256;
            int r = i >> 2, kc = i & 3;
            int gr = row0 + r;  if (gr >= M) gr = M - 1;   // clamp; rows >= M never stored
            cp_async16(base + (uint32_t)((kc * 256 + r) * 16),
                       A + (size_t)gr * K + k0 + kc * 8);
        }
        {
            int i = tid + ((tid < 256) ? 0 : 0);   // 512 chunks over 256 threads: 2 iters
#pragma unroll
            for (int u = 0; u < 2; u++) {
                int j = tid + u * 256;
                int r = j >> 2, kc = j & 3;
                cp_async16(base + 16384 + (uint32_t)((kc * 128 + r) * 16),
                           BT + (size_t)(col0 + r) * K + k0 + kc * 8);
            }
            (void)i;
        }
    };

    auto compute_stage = [&](int s) {
        const uint32_t base = sb + s * STAGE_BYTES;
        const int lrow = lid & 7;
        const int lsel = lid >> 3;
        const int a_madd  = ((lsel & 1) << 3) + lrow;
        const int a_kcadd = lsel >> 1;
        const int b_nadd  = ((lsel >> 1) << 3) + lrow;
        const int b_kcadd = lsel & 1;
        for (int ks = 0; ks < 2; ks++) {
            uint32_t ah[4][4];
#pragma unroll
            for (int mi = 0; mi < 4; mi++) {
                int m = wm * 64 + mi * 16 + a_madd;
                int kc = ks * 2 + a_kcadd;
                ldsm_x4(base + (uint32_t)((kc * 256 + m) * 16),
                        ah[mi][0], ah[mi][1], ah[mi][2], ah[mi][3]);
            }
            uint32_t bh[8][2];
#pragma unroll
            for (int nq = 0; nq < 4; nq++) {
                int n = wn * 64 + nq * 16 + b_nadd;
                int kc = ks * 2 + b_kcadd;
                ldsm_x4(base + 16384 + (uint32_t)((kc * 128 + n) * 16),
                        bh[nq*2][0], bh[nq*2][1], bh[nq*2+1][0], bh[nq*2+1][1]);
            }
#pragma unroll
            for (int mi = 0; mi < 4; mi++)
#pragma unroll
                for (int ni = 0; ni < 8; ni++)
                    mma_f16(c[mi][ni], ah[mi], bh[ni]);
        }
    };

    const int nk = K >> 5;
#pragma unroll
    for (int s = 0; s < STAGES - 1; s++) { load_stage(s, s * 32); CP_COMMIT(); }

    for (int it = 0; it < nk; it++) {
        CP_WAIT1();
        __syncthreads();
        compute_stage(it % STAGES);
        int nxt = it + STAGES - 1;
        if (nxt < nk) load_stage(nxt % STAGES, nxt * 32);
        CP_COMMIT();
    }

    // ---- epilogue ----
    const int r_in = lid >> 2;
    const int c_in = (lid & 3) * 2;
#pragma unroll
    for (int mi = 0; mi < 4; mi++) {
#pragma unroll
        for (int half = 0; half < 2; half++) {
            int gr = row0 + wm * 64 + mi * 16 + half * 8 + r_in;
            if (gr >= M) continue;
#pragma unroll
            for (int ni = 0; ni < 8; ni++) {
                int gc = col0 + wn * 64 + ni * 8 + c_in;
                float v0 = c[mi][ni][half * 2 + 0];
                float v1 = c[mi][ni][half * 2 + 1];
                if (BIAS) { v0 += bias[gc]; v1 += bias[gc + 1]; }
                if (RELU) { v0 = fmaxf(v0, 0.f); v1 = fmaxf(v1, 0.f); }
                if (OUTF32)
                    *(float2*)(C + (size_t)gr * N + gc) = make_float2(v0, v1);
                if (OUTF16) {
                    __half2 hh; hh.x = __float2half_rn(v0); hh.y = __float2half_rn(v1);
                    *(__half2*)(Ch + (size_t)gr * N + gc) = hh;
                }
            }
        }
    }
}

// ================= edge scores (fp16 k gather, q cached in smem) =================
__device__ __forceinline__ float dot8h(uint4 a, uint4 b) {
    const __half2* pa = (const __half2*)&a;
    const __half2* pb = (const __half2*)&b;
    float s = 0.f;
#pragma unroll
    for (int i = 0; i < 4; i++) {
        float2 fa = __half22float2(pa[i]);
        float2 fb = __half22float2(pb[i]);
        s = fmaf(fa.x, fb.x, s);
        s = fmaf(fa.y, fb.y, s);
    }
    return s;
}
__global__ __launch_bounds__(128)
void edge_scores_csr(const int* __restrict__ src) {
    int node = blockIdx.x;
    int t = threadIdx.x;
    int beg = g_rowptr[node], end = g_rowptr[node + 1];

    __shared__ uint4 qs[64];     // q: 512 halves = 1 KB
    if (t < 64) qs[t] = ((const uint4*)(g_qkv + (size_t)node * DQKV))[t];
    __syncthreads();

    int w = t >> 5, lane = t & 31;
    for (int e = beg + w; e < end; e += 4) {
        const uint4* kk = (const uint4*)(g_qkv + (size_t)src[e] * DQKV + DMODEL);
        // chunk j covers halves [8*(lane+32j), +8) -> head = (lane+32j)>>3
        float p0 = dot8h(kk[lane],      qs[lane]);
        float p1 = dot8h(kk[lane + 32], qs[lane + 32]);
#pragma unroll
        for (int off = 4; off; off >>= 1) {
            p0 += __shfl_xor_sync(0xffffffffu, p0, off);
            p1 += __shfl_xor_sync(0xffffffffu, p1, off);
        }
        if ((lane & 7) == 0) {
            float* out = g_e + (size_t)e * NHEAD;
            out[(lane >> 3)]     = p0 * 0.125f;
            out[4 + (lane >> 3)] = p1 * 0.125f;
        }
    }
}

// ================= per-node softmax + aggregation (fp16 v gather, fp16 out) =================
__global__ __launch_bounds__(128)
void node_aggregate(const int* __restrict__ src) {
    int node = blockIdx.x;
    int t = threadIdx.x;
    int beg = g_rowptr[node], end = g_rowptr[node + 1];

    __shared__ float s_m[NHEAD], s_rz[NHEAD];
    int head = t >> 4, sub = t & 15;
    float mx = -INFINITY;
    for (int e = beg + sub; e < end; e += 16)
        mx = fmaxf(mx, g_e[(size_t)e * NHEAD + head]);
#pragma unroll
    for (int off = 8; off; off >>= 1)
        mx = fmaxf(mx, __shfl_xor_sync(0xffffffffu, mx, off));
    float sum = 0.f;
    for (int e = beg + sub; e < end; e += 16)
        sum += __expf(g_e[(size_t)e * NHEAD + head] - mx);
#pragma unroll
    for (int off = 8; off; off >>= 1)
        sum += __shfl_xor_sync(0xffffffffu, sum, off);
    if (sub == 0) { s_m[head] = mx; s_rz[head] = (end > beg) ? (1.f / sum) : 0.f; }
    __syncthreads();

    // thread t owns halves [4t, 4t+4) of v; head = t>>4
    int h2 = t >> 4;
    float m = s_m[h2], rz = s_rz[h2];
    float4 acc = make_float4(0.f, 0.f, 0.f, 0.f);
    for (int e = beg; e < end; e++) {
        float w = __expf(g_e[(size_t)e * NHEAD + h2] - m) * rz;
        uint2 u = *(const uint2*)(g_qkv + (size_t)src[e] * DQKV + 1024 + t * 4);
        float2 f01 = __half22float2(*(const __half2*)&u.x);
        float2 f23 = __half22float2(*(const __half2*)&u.y);
        acc.x = fmaf(w, f01.x, acc.x);
        acc.y = fmaf(w, f01.y, acc.y);
        acc.z = fmaf(w, f23.x, acc.z);
        acc.w = fmaf(w, f23.y, acc.w);
    }
    __half2 h01; h01.x = __float2half_rn(acc.x); h01.y = __float2half_rn(acc.y);
    __half2 h23; h23.x = __float2half_rn(acc.z); h23.y = __float2half_rn(acc.w);
    __half2* ph = (__half2*)(g_a_h + (size_t)node * DMODEL + t * 4);
    ph[0] = h01; ph[1] = h23;
}

// ================= residual + layernorm =================
template<bool EMIT_F16>
__global__ __launch_bounds__(128)
void residual_ln(const float* __restrict__ A, const float* __restrict__ B,
                 const float* __restrict__ gamma, const float* __restrict__ beta,
                 float* __restrict__ out, __half* __restrict__ oh)
{
    int row = blockIdx.x;
    int t = threadIdx.x;
    float4 va = ((const float4*)(A + (size_t)row * DMODEL))[t];
    float4 vb = ((const float4*)(B + (size_t)row * DMODEL))[t];
    float4 v = make_float4(va.x + vb.x, va.y + vb.y, va.z + vb.z, va.w + vb.w);

    __shared__ float sh1[4], sh2[4];
    float s = v.x + v.y + v.z + v.w;
#pragma unroll
    for (int off = 16; off; off >>= 1) s += __shfl_xor_sync(0xffffffffu, s, off);
    if ((t & 31) == 0) sh1[t >> 5] = s;
    __syncthreads();
    float mu = (sh1[0] + sh1[1] + sh1[2] + sh1[3]) * (1.f / DMODEL);

    float dx = v.x - mu, dy = v.y - mu, dz = v.z - mu, dw = v.w - mu;
    float ss = dx * dx + dy * dy + dz * dz + dw * dw;
#pragma unroll
    for (int off = 16; off; off >>= 1) ss += __shfl_xor_sync(0xffffffffu, ss, off);
    if ((t & 31) == 0) sh2[t >> 5] = ss;
    __syncthreads();
    float var = (sh2[0] + sh2[1] + sh2[2] + sh2[3]) * (1.f / DMODEL);
    float rstd = rsqrtf(var + 1e-5f);

    float4 g = ((const float4*)gamma)[t];
    float4 be = ((const float4*)beta)[t];
    float o0 = dx * rstd * g.x + be.x;
    float o1 = dy * rstd * g.y + be.y;
    float o2 = dz * rstd * g.z + be.z;
    float o3 = dw * rstd * g.w + be.w;
    ((float4*)(out + (size_t)row * DMODEL))[t] = make_float4(o0, o1, o2, o3);
    if (EMIT_F16) {
        __half2 h01; h01.x = __float2half_rn(o0); h01.y = __float2half_rn(o1);
        __half2 h23; h23.x = __float2half_rn(o2); h23.y = __float2half_rn(o3);
        __half2* ph = (__half2*)(oh + (size_t)row * DMODEL + t * 4);
        ph[0] = h01; ph[1] = h23;
    }
}

// ================= launch =================
extern "C" void kernel_launch(void* const* d_in, const int* in_sizes, int n_in,
                              void* d_out, int out_size)
{
    const float* h    = (const float*)d_in[0];
    const int*   src  = (const int*)d_in[1];
    const int*   dst  = (const int*)d_in[2];
    const float* Wq   = (const float*)d_in[3];
    const float* Wk   = (const float*)d_in[4];
    const float* Wv   = (const float*)d_in[5];
    const float* Wo   = (const float*)d_in[6];
    const float* ln1g = (const float*)d_in[7];
    const float* ln1b = (const float*)d_in[8];
    const float* ln2g = (const float*)d_in[9];
    const float* ln2b = (const float*)d_in[10];
    const float* W1   = (const float*)d_in[11];
    const float* b1   = (const float*)d_in[12];
    const float* W2   = (const float*)d_in[13];
    const float* b2   = (const float*)d_in[14];
    float* out = (float*)d_out;

    float *o, *x, *y;
    cudaGetSymbolAddress((void**)&o, g_o);
    cudaGetSymbolAddress((void**)&x, g_x);
    cudaGetSymbolAddress((void**)&y, g_y);
    __half *hh, *qkv, *ah, *xh, *fh;
    cudaGetSymbolAddress((void**)&hh, g_h_h);
    cudaGetSymbolAddress((void**)&qkv, g_qkv);
    cudaGetSymbolAddress((void**)&ah, g_a_h);
    cudaGetSymbolAddress((void**)&xh, g_x_h);
    cudaGetSymbolAddress((void**)&fh, g_f_h);
    __half *wqkvT, *woT, *w1T, *w2T;
    cudaGetSymbolAddress((void**)&wqkvT, g_wqkvT);
    cudaGetSymbolAddress((void**)&woT, g_woT);
    cudaGetSymbolAddress((void**)&w1T, g_w1T);
    cudaGetSymbolAddress((void**)&w2T, g_w2T);

    cudaFuncSetAttribute(gemm_mma<false, false, false, true>,
                         cudaFuncAttributeMaxDynamicSharedMemorySize, GEMM_SMEM);
    cudaFuncSetAttribute(gemm_mma<false, false, true,  false>,
                         cudaFuncAttributeMaxDynamicSharedMemorySize, GEMM_SMEM);
    cudaFuncSetAttribute(gemm_mma<true,  true,  false, true>,
                         cudaFuncAttributeMaxDynamicSharedMemorySize, GEMM_SMEM);
    cudaFuncSetAttribute(gemm_mma<true,  false, true,  false>,
                         cudaFuncAttributeMaxDynamicSharedMemorySize, GEMM_SMEM);

    const int MB = (NNODES + 255) / 256;           // 79
    const dim3 gqkv(DQKV / 128, MB);               // (12, 79)
    const dim3 g512(DMODEL / 128, MB);             // (4, 79)
    const dim3 gff(DFFN / 128, MB);                // (16, 79)

    build_rowptr<<<(NNODES + 256) / 256, 256>>>(dst);
    cast_f16<<<(NNODES * DMODEL / 4 + 255) / 256, 256>>>(h, hh, (size_t)NNODES * DMODEL / 4);

    // fused QKV weight: rows 0-511 = Wq^T, 512-1023 = Wk^T, 1024-1535 = Wv^T
    transpose_cast<<<dim3(16, 16), dim3(32, 8)>>>(Wq, wqkvT,                 DMODEL, DMODEL);
    transpose_cast<<<dim3(16, 16), dim3(32, 8)>>>(Wk, wqkvT + 512 * DMODEL,  DMODEL, DMODEL);
    transpose_cast<<<dim3(16, 16), dim3(32, 8)>>>(Wv, wqkvT + 1024 * DMODEL, DMODEL, DMODEL);
    transpose_cast<<<dim3(16, 16), dim3(32, 8)>>>(Wo, woT, DMODEL, DMODEL);
    transpose_cast<<<dim3(DFFN / 32, 16), dim3(32, 8)>>>(W1, w1T, DMODEL, DFFN);
    transpose_cast<<<dim3(16, DFFN / 32), dim3(32, 8)>>>(W2, w2T, DFFN, DMODEL);

    gemm_mma<false, false, false, true><<<gqkv, 256, GEMM_SMEM>>>(
        hh, wqkvT, nullptr, nullptr, qkv, NNODES, DQKV, DMODEL);

    edge_scores_csr<<<NNODES, 128>>>(src);
    node_aggregate<<<NNODES, 128>>>(src);

    gemm_mma<false, false, true, false><<<g512, 256, GEMM_SMEM>>>(
        ah, woT, nullptr, o, nullptr, NNODES, DMODEL, DMODEL);
    residual_ln<true><<<NNODES, 128>>>(h, o, ln1g, ln1b, x, xh);

    gemm_mma<true, true, false, true><<<gff, 256, GEMM_SMEM>>>(
        xh, w1T, b1, nullptr, fh, NNODES, DFFN, DMODEL);
    gemm_mma<true, false, true, false><<<g512, 256, GEMM_SMEM>>>(
        fh, w2T, b2, y, nullptr, NNODES, DMODEL, DFFN);

    residual_ln<false><<<NNODES, 128>>>(x, y, ln2g, ln2b, out, nullptr);
}